// round 9
// baseline (speedup 1.0000x reference)
#include <cuda_runtime.h>
#include <cuda_bf16.h>
#include <math.h>
#include <stdint.h>

// Problem constants
#define B_  4
#define N_  4096
#define F_  256
#define U_  128
#define M_  (B_ * N_)          // 16384 rows of f
#define MAXNZ 192

// ---------------- device scratch (no allocations allowed) ----------------
__device__ float g_f  [M_ * U_];        // f = inputs @ w   [B*N, U]   (8 MB)
__device__ float g_aiT[N_ * U_];        // ai^T [N, U]                 (2 MB)
__device__ float g_ajT[N_ * U_];        // aj^T [N, U]                 (2 MB)
__device__ int   g_rows[N_ * MAXNZ];    // per-column neighbor lists   (3 MB)
__device__ int   g_cnt [N_];

// ---------------- f32x2 packed-FMA helpers ----------------
__device__ __forceinline__ unsigned long long pk2(float x, float y) {
    unsigned long long r;
    asm("mov.b64 %0, {%1,%2};" : "=l"(r) : "f"(x), "f"(y));
    return r;
}
__device__ __forceinline__ void upk2(unsigned long long v, float& x, float& y) {
    asm("mov.b64 {%0,%1}, %2;" : "=f"(x), "=f"(y) : "l"(v));
}
__device__ __forceinline__ void ffma2(unsigned long long& d, unsigned long long a,
                                      unsigned long long b) {
    asm("fma.rn.f32x2 %0, %1, %2, %0;" : "+l"(d) : "l"(a), "l"(b));
}

// ---------------- kernel 1: transpose ai, aj  ([U,N] -> [N,U]) ----------------
__global__ void transpose_k(const float* __restrict__ ai, const float* __restrict__ aj) {
    __shared__ float tile[32][33];
    const float* src = blockIdx.z ? aj : ai;
    float* dst       = blockIdx.z ? g_ajT : g_aiT;
    int n0 = blockIdx.x * 32;
    int u0 = blockIdx.y * 32;
    int tx = threadIdx.x, ty = threadIdx.y;
#pragma unroll
    for (int r = 0; r < 32; r += 8)
        tile[ty + r][tx] = src[(size_t)(u0 + ty + r) * N_ + n0 + tx];
    __syncthreads();
#pragma unroll
    for (int r = 0; r < 32; r += 8)
        dst[(size_t)(n0 + ty + r) * U_ + u0 + tx] = tile[tx][ty + r];
}

// ---------------- kernel 2: f = inputs @ w  (16384x256 @ 256x128, fp32/f32x2) ----
__global__ __launch_bounds__(256) void gemm_f(const float* __restrict__ A,
                                              const float* __restrict__ W) {
    __shared__ float As[32][132];   // [BK][BM+4], transposed A tile
    __shared__ float Bs[32][128];   // [BK][BN]
    const int tid = threadIdx.x;
    const int m0  = blockIdx.x * 128;
    const int tm  = (tid >> 4) << 3;
    const int tn  = (tid & 15) << 3;

    unsigned long long acc[8][4];
#pragma unroll
    for (int i = 0; i < 8; i++)
#pragma unroll
        for (int j = 0; j < 4; j++) acc[i][j] = 0ull;

    for (int k0 = 0; k0 < F_; k0 += 32) {
#pragma unroll
        for (int r = 0; r < 4; r++) {
            int idx = tid + 256 * r;
            int row = idx >> 3;
            int c4  = idx & 7;
            float4 v = *(const float4*)(A + (size_t)(m0 + row) * F_ + k0 + c4 * 4);
            As[c4 * 4 + 0][row] = v.x;
            As[c4 * 4 + 1][row] = v.y;
            As[c4 * 4 + 2][row] = v.z;
            As[c4 * 4 + 3][row] = v.w;
        }
#pragma unroll
        for (int r = 0; r < 4; r++) {
            int idx = tid + 256 * r;
            int row = idx >> 5;
            int c4  = idx & 31;
            *(float4*)&Bs[row][c4 * 4] =
                *(const float4*)(W + (size_t)(k0 + row) * U_ + c4 * 4);
        }
        __syncthreads();
#pragma unroll
        for (int kk = 0; kk < 32; kk++) {
            float a[8];
            *(float4*)&a[0] = *(const float4*)&As[kk][tm];
            *(float4*)&a[4] = *(const float4*)&As[kk][tm + 4];
            ulonglong2 b01 = *(const ulonglong2*)&Bs[kk][tn];
            ulonglong2 b23 = *(const ulonglong2*)&Bs[kk][tn + 4];
            unsigned long long b[4] = {b01.x, b01.y, b23.x, b23.y};
#pragma unroll
            for (int i = 0; i < 8; i++) {
                unsigned long long ar = pk2(a[i], a[i]);
#pragma unroll
                for (int j = 0; j < 4; j++) ffma2(acc[i][j], ar, b[j]);
            }
        }
        __syncthreads();
    }
#pragma unroll
    for (int i = 0; i < 8; i++) {
        float x0, x1, x2, x3, x4, x5, x6, x7;
        upk2(acc[i][0], x0, x1);
        upk2(acc[i][1], x2, x3);
        upk2(acc[i][2], x4, x5);
        upk2(acc[i][3], x6, x7);
        float* cp = g_f + (size_t)(m0 + tm + i) * U_ + tn;
        *(float4*)cp       = make_float4(x0, x1, x2, x3);
        *(float4*)(cp + 4) = make_float4(x4, x5, x6, x7);
    }
}

// ---------------- kernel 3: build per-column neighbor lists (deterministic) -----
__global__ __launch_bounds__(128) void build_k(const float* __restrict__ adj) {
    const int j = blockIdx.x;
    const int t = threadIdx.x;
    __shared__ int sc[128];
    const float* row = adj + (size_t)j * N_;

    int cnt = 0;
#pragma unroll
    for (int k = 0; k < 32; k++) {
        int i = k * 128 + t;
        float v = row[i];
        if (i == j || v > 0.0f) cnt++;
    }
    sc[t] = cnt;
    __syncthreads();
    for (int off = 1; off < 128; off <<= 1) {
        int add = (t >= off) ? sc[t - off] : 0;
        __syncthreads();
        sc[t] += add;
        __syncthreads();
    }
    int pos = sc[t] - cnt;
    int* dst = g_rows + (size_t)j * MAXNZ;
#pragma unroll
    for (int k = 0; k < 32; k++) {
        int i = k * 128 + t;
        float v = row[i];
        if (i == j) {
            if (pos < MAXNZ) dst[pos] = i | ((v > 0.0f) ? 0x10000 : 0);
            pos++;
        } else if (v > 0.0f) {
            if (pos < MAXNZ) dst[pos] = i;
            pos++;
        }
    }
    if (t == 127) g_cnt[j] = (sc[127] < MAXNZ) ? sc[127] : MAXNZ;
}

// ---------------- kernel 4: single-pass online-softmax column kernel ------------
// one block per column j, warp b handles batch b. float4 layout: lane owns u=lane*4..+3
__global__ __launch_bounds__(128) void col_k(float* __restrict__ out,
                                             float* __restrict__ attn,
                                             int write_attn) {
    const int j    = blockIdx.x;
    const int warp = threadIdx.x >> 5;
    const int lane = threadIdx.x & 31;

    __shared__ float s_lg[B_][MAXNZ];
    __shared__ int   s_rows[MAXNZ];

    const int nnz = g_cnt[j];
    for (int e = threadIdx.x; e < nnz; e += 128)
        s_rows[e] = g_rows[(size_t)j * MAXNZ + e];
    __syncthreads();

    const float* fb = g_f + (size_t)warp * N_ * U_;
    const float4 fj4 = *(const float4*)(fb + (size_t)j * U_ + lane * 4);
    const float4 ai4 = *(const float4*)(g_aiT + (size_t)j * U_ + lane * 4);

    float  m    = -3.0e38f;
    float  ssum = 0.0f;
    float4 acc  = make_float4(0.f, 0.f, 0.f, 0.f);

    // prefetch edge 0
    int    enc = s_rows[0];
    float4 fi4 = *(const float4*)(fb + (size_t)(enc & 0xFFFF) * U_ + lane * 4);
    float4 aj4 = *(const float4*)(g_ajT + (size_t)(enc & 0xFFFF) * U_ + lane * 4);

    for (int e = 0; e < nnz; e++) {
        const int    cenc = enc;
        const float4 cfi  = fi4;
        const float4 caj  = aj4;
        if (e + 1 < nnz) {                       // prefetch next edge (MLP)
            enc = s_rows[e + 1];
            int i = enc & 0xFFFF;
            fi4 = *(const float4*)(fb + (size_t)i * U_ + lane * 4);
            aj4 = *(const float4*)(g_ajT + (size_t)i * U_ + lane * 4);
        }
        // partial of logit = f[i,:].ai[:,j] + f[j,:].aj[:,i]
        float part;
        part = cfi.x * ai4.x;
        part = fmaf(cfi.y, ai4.y, part);
        part = fmaf(cfi.z, ai4.z, part);
        part = fmaf(cfi.w, ai4.w, part);
        part = fmaf(fj4.x, caj.x, part);
        part = fmaf(fj4.y, caj.y, part);
        part = fmaf(fj4.z, caj.z, part);
        part = fmaf(fj4.w, caj.w, part);
#pragma unroll
        for (int off = 16; off; off >>= 1)
            part += __shfl_xor_sync(0xFFFFFFFFu, part, off);
        const float lg = part + ((cenc & 0x10000) ? 1.0e9f : 0.0f);
        if (lane == 0) s_lg[warp][e] = lg;

        // online softmax update
        const float newm  = fmaxf(m, lg);
        const float scale = expf(m - newm);      // 0 on first iter (m=-3e38)
        const float p     = expf(lg - newm);
        ssum  = fmaf(ssum, scale, p);
        acc.x = fmaf(acc.x, scale, p * cfi.x);
        acc.y = fmaf(acc.y, scale, p * cfi.y);
        acc.z = fmaf(acc.z, scale, p * cfi.z);
        acc.w = fmaf(acc.w, scale, p * cfi.w);
        m = newm;
    }
    __syncwarp();

    const float inv = 1.0f / ssum;

    // scatter attn nonzeros
    if (write_attn) {
        for (int e = lane; e < nnz; e += 32) {
            int i = s_rows[e] & 0xFFFF;
            attn[((size_t)warp * N_ + i) * N_ + j] = expf(s_lg[warp][e] - m) * inv;
        }
    }

    // out[b,j,:] = relu(acc * inv)
    float4 o;
    o.x = fmaxf(acc.x * inv, 0.0f);
    o.y = fmaxf(acc.y * inv, 0.0f);
    o.z = fmaxf(acc.z * inv, 0.0f);
    o.w = fmaxf(acc.w * inv, 0.0f);
    *(float4*)(out + ((size_t)warp * N_ + j) * U_ + lane * 4) = o;
}

// ---------------- launch (fork/join graph for overlap) ----------------
extern "C" void kernel_launch(void* const* d_in, const int* in_sizes, int n_in,
                              void* d_out, int out_size) {
    const float* inputs = (const float*)d_in[0];   // [B,N,F]
    const float* w      = (const float*)d_in[1];   // [F,U]
    const float* ai     = (const float*)d_in[2];   // [U,N]
    const float* aj     = (const float*)d_in[3];   // [U,N]
    const float* adj    = (const float*)d_in[4];   // [N,N]

    const size_t OUT1 = (size_t)B_ * N_ * U_;
    const size_t ATTN = (size_t)B_ * N_ * N_;
    float* out_relu = (float*)d_out;
    float* attn = nullptr;
    if ((size_t)out_size >= OUT1 + ATTN) attn = (float*)d_out + OUT1;

    // Lazy one-time stream/event creation. Happens on the (uncaptured)
    // correctness call; subsequent captured calls issue identical work.
    static cudaStream_t st[3];
    static cudaEvent_t  evRoot, evDone[3];
    static int streams_ok = -1;
    if (streams_ok < 0) {
        streams_ok = 1;
        for (int k = 0; k < 3; k++)
            if (cudaStreamCreateWithFlags(&st[k], cudaStreamNonBlocking) != cudaSuccess)
                streams_ok = 0;
        if (cudaEventCreateWithFlags(&evRoot, cudaEventDisableTiming) != cudaSuccess)
            streams_ok = 0;
        for (int k = 0; k < 3; k++)
            if (cudaEventCreateWithFlags(&evDone[k], cudaEventDisableTiming) != cudaSuccess)
                streams_ok = 0;
    }

    if (streams_ok) {
        cudaEventRecord(evRoot, 0);
        // branch 0: memset attn (DRAM-write bound)
        cudaStreamWaitEvent(st[0], evRoot, 0);
        if (attn) cudaMemsetAsync(attn, 0, ATTN * sizeof(float), st[0]);
        cudaEventRecord(evDone[0], st[0]);
        // branch 1: adjacency scan
        cudaStreamWaitEvent(st[1], evRoot, 0);
        build_k<<<N_, 128, 0, st[1]>>>(adj);
        cudaEventRecord(evDone[1], st[1]);
        // branch 2: transposes
        cudaStreamWaitEvent(st[2], evRoot, 0);
        transpose_k<<<dim3(N_ / 32, U_ / 32, 2), dim3(32, 8), 0, st[2]>>>(ai, aj);
        cudaEventRecord(evDone[2], st[2]);
        // main: f-GEMM
        gemm_f<<<M_ / 128, 256>>>(inputs, w);
        // join
        for (int k = 0; k < 3; k++) cudaStreamWaitEvent(0, evDone[k], 0);
        col_k<<<N_, 128>>>(out_relu, attn, attn != nullptr);
    } else {
        if (attn) cudaMemsetAsync(attn, 0, ATTN * sizeof(float), 0);
        transpose_k<<<dim3(N_ / 32, U_ / 32, 2), dim3(32, 8)>>>(ai, aj);
        gemm_f<<<M_ / 128, 256>>>(inputs, w);
        build_k<<<N_, 128>>>(adj);
        col_k<<<N_, 128>>>(out_relu, attn, attn != nullptr);
    }
}

// round 11
// speedup vs baseline: 1.0285x; 1.0285x over previous
#include <cuda_runtime.h>
#include <cuda_bf16.h>
#include <math.h>
#include <stdint.h>

// Problem constants
#define B_  4
#define N_  4096
#define F_  256
#define U_  128
#define M_  (B_ * N_)          // 16384 rows of f
#define MAXNZ 192

// Front-kernel block roles: 128 GEMM blocks, then 7168 interleaved
// (build:transpose:fill = 4:1:2 per group of 7).
#define NB_GEMM   128
#define NB_REST   7168
#define NB_TOTAL  (NB_GEMM + NB_REST)   // 7296
#define FILL_SLABS 2048                  // 2048 slabs * 256 thr * 32 f4 = 16M f4

// ---------------- device scratch (no allocations allowed) ----------------
__device__ float g_f  [M_ * U_];        // f = inputs @ w   [B*N, U]   (8 MB)
__device__ float g_aiT[N_ * U_];        // ai^T [N, U]                 (2 MB)
__device__ float g_ajT[N_ * U_];        // aj^T [N, U]                 (2 MB)
__device__ int   g_rows[N_ * MAXNZ];    // per-column neighbor lists   (3 MB)
__device__ int   g_cnt [N_];

// ---------------- f32x2 packed-FMA helpers ----------------
__device__ __forceinline__ unsigned long long pk2(float x, float y) {
    unsigned long long r;
    asm("mov.b64 %0, {%1,%2};" : "=l"(r) : "f"(x), "f"(y));
    return r;
}
__device__ __forceinline__ void upk2(unsigned long long v, float& x, float& y) {
    asm("mov.b64 {%0,%1}, %2;" : "=f"(x), "=f"(y) : "l"(v));
}
__device__ __forceinline__ void ffma2(unsigned long long& d, unsigned long long a,
                                      unsigned long long b) {
    asm("fma.rn.f32x2 %0, %1, %2, %0;" : "+l"(d) : "l"(a), "l"(b));
}

// ================= fused front kernel: GEMM + build + transpose + fill =========
__global__ __launch_bounds__(256) void front_k(const float* __restrict__ A,
                                               const float* __restrict__ W,
                                               const float* __restrict__ ai,
                                               const float* __restrict__ aj,
                                               const float* __restrict__ adj,
                                               float* __restrict__ attn) {
    const int bid = blockIdx.x;
    const int tid = threadIdx.x;

    if (bid < NB_GEMM) {
        // ---------------- role GEMM: f = inputs @ w (128x128 tile) ----------------
        __shared__ float As[32][132];
        __shared__ float Bs[32][128];
        const int m0 = bid * 128;
        const int tm = (tid >> 4) << 3;
        const int tn = (tid & 15) << 3;

        unsigned long long acc[8][4];
#pragma unroll
        for (int i = 0; i < 8; i++)
#pragma unroll
            for (int j = 0; j < 4; j++) acc[i][j] = 0ull;

        for (int k0 = 0; k0 < F_; k0 += 32) {
#pragma unroll
            for (int r = 0; r < 4; r++) {
                int idx = tid + 256 * r;
                int row = idx >> 3;
                int c4  = idx & 7;
                float4 v = *(const float4*)(A + (size_t)(m0 + row) * F_ + k0 + c4 * 4);
                As[c4 * 4 + 0][row] = v.x;
                As[c4 * 4 + 1][row] = v.y;
                As[c4 * 4 + 2][row] = v.z;
                As[c4 * 4 + 3][row] = v.w;
            }
#pragma unroll
            for (int r = 0; r < 4; r++) {
                int idx = tid + 256 * r;
                int row = idx >> 5;
                int c4  = idx & 31;
                *(float4*)&Bs[row][c4 * 4] =
                    *(const float4*)(W + (size_t)(k0 + row) * U_ + c4 * 4);
            }
            __syncthreads();
#pragma unroll
            for (int kk = 0; kk < 32; kk++) {
                float a[8];
                *(float4*)&a[0] = *(const float4*)&As[kk][tm];
                *(float4*)&a[4] = *(const float4*)&As[kk][tm + 4];
                ulonglong2 b01 = *(const ulonglong2*)&Bs[kk][tn];
                ulonglong2 b23 = *(const ulonglong2*)&Bs[kk][tn + 4];
                unsigned long long b[4] = {b01.x, b01.y, b23.x, b23.y};
#pragma unroll
                for (int i = 0; i < 8; i++) {
                    unsigned long long ar = pk2(a[i], a[i]);
#pragma unroll
                    for (int j = 0; j < 4; j++) ffma2(acc[i][j], ar, b[j]);
                }
            }
            __syncthreads();
        }
#pragma unroll
        for (int i = 0; i < 8; i++) {
            float x0, x1, x2, x3, x4, x5, x6, x7;
            upk2(acc[i][0], x0, x1);
            upk2(acc[i][1], x2, x3);
            upk2(acc[i][2], x4, x5);
            upk2(acc[i][3], x6, x7);
            float* cp = g_f + (size_t)(m0 + tm + i) * U_ + tn;
            *(float4*)cp       = make_float4(x0, x1, x2, x3);
            *(float4*)(cp + 4) = make_float4(x4, x5, x6, x7);
        }
        return;
    }

    const int rem = bid - NB_GEMM;      // [0, 7168)
    const int g   = rem / 7;            // [0, 1024)
    const int r   = rem - g * 7;        // [0, 7)

    if (r < 4) {
        // ---------------- role BUILD: neighbor list for column j -----------------
        const int j = g * 4 + r;        // [0, 4096)
        __shared__ int sc[256];
        const float* row = adj + (size_t)j * N_;

        int cnt = 0;
#pragma unroll
        for (int k = 0; k < 16; k++) {
            int i = k * 256 + tid;
            float v = row[i];
            if (i == j || v > 0.0f) cnt++;
        }
        sc[tid] = cnt;
        __syncthreads();
        for (int off = 1; off < 256; off <<= 1) {
            int add = (tid >= off) ? sc[tid - off] : 0;
            __syncthreads();
            sc[tid] += add;
            __syncthreads();
        }
        int pos = sc[tid] - cnt;
        int* dst = g_rows + (size_t)j * MAXNZ;
#pragma unroll
        for (int k = 0; k < 16; k++) {
            int i = k * 256 + tid;
            float v = row[i];
            if (i == j) {
                if (pos < MAXNZ) dst[pos] = i | ((v > 0.0f) ? 0x10000 : 0);
                pos++;
            } else if (v > 0.0f) {
                if (pos < MAXNZ) dst[pos] = i;
                pos++;
            }
        }
        if (tid == 255) g_cnt[j] = (sc[255] < MAXNZ) ? sc[255] : MAXNZ;
        return;
    }

    if (r == 4) {
        // ---------------- role TRANSPOSE: one 32x32 tile of ai or aj --------------
        // g in [0,1024): 512 tiles per matrix (128 n-tiles x 4 u-tiles)
        __shared__ float tile[32][33];
        const int z   = g >> 9;          // 0 = ai, 1 = aj
        const int t2  = g & 511;
        const int n0  = (t2 & 127) * 32;
        const int u0  = (t2 >> 7) * 32;
        const float* src = z ? aj : ai;
        float* dst       = z ? g_ajT : g_aiT;
        const int tx = tid & 31, ty = tid >> 5;   // 32 x 8
#pragma unroll
        for (int rr = 0; rr < 32; rr += 8)
            tile[ty + rr][tx] = src[(size_t)(u0 + ty + rr) * N_ + n0 + tx];
        __syncthreads();
#pragma unroll
        for (int rr = 0; rr < 32; rr += 8)
            dst[(size_t)(n0 + ty + rr) * U_ + u0 + tx] = tile[tx][ty + rr];
        return;
    }

    // ---------------- role FILL: zero a slab of attn (streaming stores) ----------
    if (attn == nullptr) return;
    const int slab = g * 2 + (r - 5);   // [0, 2048)
    float4* p = (float4*)attn;
    const float4 z4 = make_float4(0.f, 0.f, 0.f, 0.f);
    size_t idx = (size_t)slab * 256 + tid;
#pragma unroll
    for (int k = 0; k < 32; k++) {
        __stcs(&p[idx], z4);            // evict-first: don't thrash L2
        idx += (size_t)FILL_SLABS * 256;
    }
}

// ---------------- col kernel: online-softmax, 4-edge batches --------------------
// one block per column j, warp b handles batch b. lane owns u = lane*4 .. +3
__global__ __launch_bounds__(128) void col_k(float* __restrict__ out,
                                             float* __restrict__ attn,
                                             int write_attn) {
    const int j    = blockIdx.x;
    const int warp = threadIdx.x >> 5;
    const int lane = threadIdx.x & 31;

    __shared__ float s_lg[B_][MAXNZ];
    __shared__ int   s_rows[MAXNZ];

    const int nnz = g_cnt[j];
    for (int e = threadIdx.x; e < nnz; e += 128)
        s_rows[e] = g_rows[(size_t)j * MAXNZ + e];
    __syncthreads();

    const float* fb = g_f + (size_t)warp * N_ * U_;
    const float4 fj4 = *(const float4*)(fb + (size_t)j * U_ + lane * 4);
    const float4 ai4 = *(const float4*)(g_aiT + (size_t)j * U_ + lane * 4);

    float  m    = -3.0e38f;
    float  ssum = 0.0f;
    float4 acc  = make_float4(0.f, 0.f, 0.f, 0.f);

    int e = 0;
    for (; e + 4 <= nnz; e += 4) {
        int    enc[4];
        float4 fi[4], aj[4];
#pragma unroll
        for (int q = 0; q < 4; q++) {
            enc[q] = s_rows[e + q];
            int i  = enc[q] & 0xFFFF;
            fi[q]  = *(const float4*)(fb + (size_t)i * U_ + lane * 4);
            aj[q]  = *(const float4*)(g_ajT + (size_t)i * U_ + lane * 4);
        }
        float part[4];
#pragma unroll
        for (int q = 0; q < 4; q++) {
            float p;
            p = fi[q].x * ai4.x;
            p = fmaf(fi[q].y, ai4.y, p);
            p = fmaf(fi[q].z, ai4.z, p);
            p = fmaf(fi[q].w, ai4.w, p);
            p = fmaf(fj4.x, aj[q].x, p);
            p = fmaf(fj4.y, aj[q].y, p);
            p = fmaf(fj4.z, aj[q].z, p);
            p = fmaf(fj4.w, aj[q].w, p);
            part[q] = p;
        }
#pragma unroll
        for (int off = 16; off; off >>= 1) {
#pragma unroll
            for (int q = 0; q < 4; q++)
                part[q] += __shfl_xor_sync(0xFFFFFFFFu, part[q], off);
        }
        float lg[4];
#pragma unroll
        for (int q = 0; q < 4; q++) {
            lg[q] = part[q] + ((enc[q] & 0x10000) ? 1.0e9f : 0.0f);
            if (lane == 0) s_lg[warp][e + q] = lg[q];
        }
        float bm = fmaxf(fmaxf(lg[0], lg[1]), fmaxf(lg[2], lg[3]));
        float newm  = fmaxf(m, bm);
        float scale = expf(m - newm);
        float p0 = expf(lg[0] - newm);
        float p1 = expf(lg[1] - newm);
        float p2 = expf(lg[2] - newm);
        float p3 = expf(lg[3] - newm);
        ssum = fmaf(ssum, scale, (p0 + p1) + (p2 + p3));
        acc.x = fmaf(acc.x, scale, fmaf(p0, fi[0].x, fmaf(p1, fi[1].x, fmaf(p2, fi[2].x, p3 * fi[3].x))));
        acc.y = fmaf(acc.y, scale, fmaf(p0, fi[0].y, fmaf(p1, fi[1].y, fmaf(p2, fi[2].y, p3 * fi[3].y))));
        acc.z = fmaf(acc.z, scale, fmaf(p0, fi[0].z, fmaf(p1, fi[1].z, fmaf(p2, fi[2].z, p3 * fi[3].z))));
        acc.w = fmaf(acc.w, scale, fmaf(p0, fi[0].w, fmaf(p1, fi[1].w, fmaf(p2, fi[2].w, p3 * fi[3].w))));
        m = newm;
    }
    for (; e < nnz; e++) {
        int enc = s_rows[e];
        int i   = enc & 0xFFFF;
        float4 cfi = *(const float4*)(fb + (size_t)i * U_ + lane * 4);
        float4 caj = *(const float4*)(g_ajT + (size_t)i * U_ + lane * 4);
        float part;
        part = cfi.x * ai4.x;
        part = fmaf(cfi.y, ai4.y, part);
        part = fmaf(cfi.z, ai4.z, part);
        part = fmaf(cfi.w, ai4.w, part);
        part = fmaf(fj4.x, caj.x, part);
        part = fmaf(fj4.y, caj.y, part);
        part = fmaf(fj4.z, caj.z, part);
        part = fmaf(fj4.w, caj.w, part);
#pragma unroll
        for (int off = 16; off; off >>= 1)
            part += __shfl_xor_sync(0xFFFFFFFFu, part, off);
        float lg = part + ((enc & 0x10000) ? 1.0e9f : 0.0f);
        if (lane == 0) s_lg[warp][e] = lg;
        float newm  = fmaxf(m, lg);
        float scale = expf(m - newm);
        float p     = expf(lg - newm);
        ssum  = fmaf(ssum, scale, p);
        acc.x = fmaf(acc.x, scale, p * cfi.x);
        acc.y = fmaf(acc.y, scale, p * cfi.y);
        acc.z = fmaf(acc.z, scale, p * cfi.z);
        acc.w = fmaf(acc.w, scale, p * cfi.w);
        m = newm;
    }
    __syncwarp();

    const float inv = 1.0f / ssum;

    if (write_attn) {
        for (int k = lane; k < nnz; k += 32) {
            int i = s_rows[k] & 0xFFFF;
            attn[((size_t)warp * N_ + i) * N_ + j] = expf(s_lg[warp][k] - m) * inv;
        }
    }

    float4 o;
    o.x = fmaxf(acc.x * inv, 0.0f);
    o.y = fmaxf(acc.y * inv, 0.0f);
    o.z = fmaxf(acc.z * inv, 0.0f);
    o.w = fmaxf(acc.w * inv, 0.0f);
    *(float4*)(out + ((size_t)warp * N_ + j) * U_ + lane * 4) = o;
}

// ---------------- launch: simple 2-node chain on the capture stream ------------
extern "C" void kernel_launch(void* const* d_in, const int* in_sizes, int n_in,
                              void* d_out, int out_size) {
    const float* inputs = (const float*)d_in[0];   // [B,N,F]
    const float* w      = (const float*)d_in[1];   // [F,U]
    const float* ai     = (const float*)d_in[2];   // [U,N]
    const float* aj     = (const float*)d_in[3];   // [U,N]
    const float* adj    = (const float*)d_in[4];   // [N,N]

    const size_t OUT1 = (size_t)B_ * N_ * U_;
    const size_t ATTN = (size_t)B_ * N_ * N_;
    float* out_relu = (float*)d_out;
    float* attn = nullptr;
    if ((size_t)out_size >= OUT1 + ATTN) attn = (float*)d_out + OUT1;

    front_k<<<NB_TOTAL, 256>>>(inputs, w, ai, aj, adj, attn);
    col_k<<<N_, 128>>>(out_relu, attn, attn != nullptr);
}

// round 13
// speedup vs baseline: 1.0343x; 1.0057x over previous
#include <cuda_runtime.h>
#include <cuda_bf16.h>
#include <math.h>
#include <stdint.h>

// Problem constants
#define B_  4
#define N_  4096
#define F_  256
#define U_  128
#define M_  (B_ * N_)          // 16384 rows of f
#define MAXNZ 192

// front_k roles: 256 GEMM blocks (BM=64), then 7168 interleaved
// (build:transpose:fill = 4:1:2 per group of 7).
#define NB_GEMM    256
#define NB_REST    7168
#define NB_FRONT   (NB_GEMM + NB_REST)      // 7424
#define FRONT_FILL 2048                      // fill blocks in front_k (256 thr)
#define COL_FILL   2048                      // fill blocks in col_k   (128 thr)
#define ATTN_F4    16777216                  // 268MB / 16B
#define HALF_F4    8388608                   // front_k fills [0, HALF), col_k the rest

// ---------------- device scratch (no allocations allowed) ----------------
__device__ float g_f   [M_ * U_];            // f = inputs @ w  [B*N, U]     (8 MB)
__device__ float g_aiT [N_ * U_];            // ai^T [N, U]                  (2 MB)
__device__ float g_ajT [N_ * U_];            // aj^T [N, U]                  (2 MB)
__device__ int   g_rows[N_ * MAXNZ];         // per-column neighbor lists    (3 MB)
__device__ int   g_cnt [N_];
__device__ float g_pvals[B_ * N_ * MAXNZ];   // normalized attn nonzeros    (12.6 MB)

// ---------------- f32x2 packed-FMA helpers ----------------
__device__ __forceinline__ unsigned long long pk2(float x, float y) {
    unsigned long long r;
    asm("mov.b64 %0, {%1,%2};" : "=l"(r) : "f"(x), "f"(y));
    return r;
}
__device__ __forceinline__ void upk2(unsigned long long v, float& x, float& y) {
    asm("mov.b64 {%0,%1}, %2;" : "=f"(x), "=f"(y) : "l"(v));
}
__device__ __forceinline__ void ffma2(unsigned long long& d, unsigned long long a,
                                      unsigned long long b) {
    asm("fma.rn.f32x2 %0, %1, %2, %0;" : "+l"(d) : "l"(a), "l"(b));
}

// ================= front kernel: GEMM + build + transpose + fill(half) =========
__global__ __launch_bounds__(256) void front_k(const float* __restrict__ A,
                                               const float* __restrict__ W,
                                               const float* __restrict__ ai,
                                               const float* __restrict__ aj,
                                               const float* __restrict__ adj,
                                               float* __restrict__ attn) {
    const int bid = blockIdx.x;
    const int tid = threadIdx.x;

    if (bid < NB_GEMM) {
        // -------- role GEMM: f = inputs @ w, 64x128 tile --------------------------
        __shared__ float As[32][68];    // [BK][BM+4]
        __shared__ float Bs[32][128];
        const int m0 = bid * 64;
        const int tm = (tid >> 4) << 2;    // 0..60 step 4
        const int tn = (tid & 15) << 3;    // 0..120 step 8

        unsigned long long acc[4][4];
#pragma unroll
        for (int i = 0; i < 4; i++)
#pragma unroll
            for (int j = 0; j < 4; j++) acc[i][j] = 0ull;

        for (int k0 = 0; k0 < F_; k0 += 32) {
            // A tile 64x32 -> As transposed (512 f4, 2 per thread)
#pragma unroll
            for (int r = 0; r < 2; r++) {
                int idx = tid + 256 * r;
                int row = idx >> 3;
                int c4  = idx & 7;
                float4 v = *(const float4*)(A + (size_t)(m0 + row) * F_ + k0 + c4 * 4);
                As[c4 * 4 + 0][row] = v.x;
                As[c4 * 4 + 1][row] = v.y;
                As[c4 * 4 + 2][row] = v.z;
                As[c4 * 4 + 3][row] = v.w;
            }
            // W tile 32x128 = 1024 f4 -> 4 per thread  (FIX: was 1/thread, rows 8-31 stale)
#pragma unroll
            for (int r = 0; r < 4; r++) {
                int idx = tid + 256 * r;
                int row = idx >> 5;          // 0..31
                int c4  = idx & 31;          // 0..31
                *(float4*)&Bs[row][c4 * 4] =
                    *(const float4*)(W + (size_t)(k0 + row) * U_ + c4 * 4);
            }
            __syncthreads();
#pragma unroll
            for (int kk = 0; kk < 32; kk++) {
                float a[4];
                *(float4*)&a[0] = *(const float4*)&As[kk][tm];
                ulonglong2 b01 = *(const ulonglong2*)&Bs[kk][tn];
                ulonglong2 b23 = *(const ulonglong2*)&Bs[kk][tn + 4];
                unsigned long long b[4] = {b01.x, b01.y, b23.x, b23.y};
#pragma unroll
                for (int i = 0; i < 4; i++) {
                    unsigned long long ar = pk2(a[i], a[i]);
#pragma unroll
                    for (int j = 0; j < 4; j++) ffma2(acc[i][j], ar, b[j]);
                }
            }
            __syncthreads();
        }
#pragma unroll
        for (int i = 0; i < 4; i++) {
            float x0, x1, x2, x3, x4, x5, x6, x7;
            upk2(acc[i][0], x0, x1);
            upk2(acc[i][1], x2, x3);
            upk2(acc[i][2], x4, x5);
            upk2(acc[i][3], x6, x7);
            float* cp = g_f + (size_t)(m0 + tm + i) * U_ + tn;
            *(float4*)cp       = make_float4(x0, x1, x2, x3);
            *(float4*)(cp + 4) = make_float4(x4, x5, x6, x7);
        }
        return;
    }

    const int rem = bid - NB_GEMM;      // [0, 7168)
    const int g   = rem / 7;            // [0, 1024)
    const int r   = rem - g * 7;        // [0, 7)

    if (r < 4) {
        // -------- role BUILD: neighbor list for column j --------------------------
        const int j = g * 4 + r;
        __shared__ int sc[256];
        const float* row = adj + (size_t)j * N_;

        int cnt = 0;
#pragma unroll
        for (int k = 0; k < 16; k++) {
            int i = k * 256 + tid;
            float v = row[i];
            if (i == j || v > 0.0f) cnt++;
        }
        sc[tid] = cnt;
        __syncthreads();
        for (int off = 1; off < 256; off <<= 1) {
            int add = (tid >= off) ? sc[tid - off] : 0;
            __syncthreads();
            sc[tid] += add;
            __syncthreads();
        }
        int pos = sc[tid] - cnt;
        int* dst = g_rows + (size_t)j * MAXNZ;
#pragma unroll
        for (int k = 0; k < 16; k++) {
            int i = k * 256 + tid;
            float v = row[i];
            if (i == j) {
                if (pos < MAXNZ) dst[pos] = i | ((v > 0.0f) ? 0x10000 : 0);
                pos++;
            } else if (v > 0.0f) {
                if (pos < MAXNZ) dst[pos] = i;
                pos++;
            }
        }
        if (tid == 255) g_cnt[j] = (sc[255] < MAXNZ) ? sc[255] : MAXNZ;
        return;
    }

    if (r == 4) {
        // -------- role TRANSPOSE: one 32x32 tile of ai or aj ----------------------
        __shared__ float tile[32][33];
        const int z   = g >> 9;
        const int t2  = g & 511;
        const int n0  = (t2 & 127) * 32;
        const int u0  = (t2 >> 7) * 32;
        const float* src = z ? aj : ai;
        float* dst       = z ? g_ajT : g_aiT;
        const int tx = tid & 31, ty = tid >> 5;
#pragma unroll
        for (int rr = 0; rr < 32; rr += 8)
            tile[ty + rr][tx] = src[(size_t)(u0 + ty + rr) * N_ + n0 + tx];
        __syncthreads();
#pragma unroll
        for (int rr = 0; rr < 32; rr += 8)
            dst[(size_t)(n0 + ty + rr) * U_ + u0 + tx] = tile[tx][ty + rr];
        return;
    }

    // -------- role FILL: zero first half of attn (streaming stores) --------------
    if (attn == nullptr) return;
    const int fb = g * 2 + (r - 5);     // [0, 2048)
    float4* p = (float4*)attn;
    const float4 z4 = make_float4(0.f, 0.f, 0.f, 0.f);
    size_t idx = (size_t)fb * 256 + tid;
#pragma unroll
    for (int k = 0; k < 16; k++) {
        __stcs(&p[idx], z4);
        idx += (size_t)FRONT_FILL * 256;
    }
}

// ======= col kernel: 4096 column blocks + 2048 fill blocks (second half) =======
// column block: one column j, warp b = batch b. lane owns u = lane*4 .. +3
__global__ __launch_bounds__(128) void col_k(float* __restrict__ out,
                                             float* __restrict__ attn,
                                             int write_attn) {
    const int bid = blockIdx.x;
    const int grp = bid / 3;
    const int rr  = bid - grp * 3;

    if (rr == 2) {
        // -------- role FILL: zero second half of attn -----------------------------
        if (attn == nullptr) return;
        float4* p = (float4*)attn;
        const float4 z4 = make_float4(0.f, 0.f, 0.f, 0.f);
        size_t idx = (size_t)HALF_F4 + (size_t)grp * 128 + threadIdx.x;
#pragma unroll
        for (int k = 0; k < 32; k++) {
            __stcs(&p[idx], z4);
            idx += (size_t)COL_FILL * 128;
        }
        return;
    }

    const int j    = grp * 2 + rr;      // [0, 4096)
    const int warp = threadIdx.x >> 5;
    const int lane = threadIdx.x & 31;

    __shared__ float s_lg[B_][MAXNZ];
    __shared__ int   s_rows[MAXNZ];

    const int nnz = g_cnt[j];
    for (int e = threadIdx.x; e < nnz; e += 128)
        s_rows[e] = g_rows[(size_t)j * MAXNZ + e];
    __syncthreads();

    const float* fb = g_f + (size_t)warp * N_ * U_;
    const float4 fj4 = *(const float4*)(fb + (size_t)j * U_ + lane * 4);
    const float4 ai4 = *(const float4*)(g_aiT + (size_t)j * U_ + lane * 4);

    float  m    = -3.0e38f;
    float  ssum = 0.0f;
    float4 acc  = make_float4(0.f, 0.f, 0.f, 0.f);

    int e = 0;
    for (; e + 4 <= nnz; e += 4) {
        int    enc[4];
        float4 fi[4], aj[4];
#pragma unroll
        for (int q = 0; q < 4; q++) {
            enc[q] = s_rows[e + q];
            int i  = enc[q] & 0xFFFF;
            fi[q]  = *(const float4*)(fb + (size_t)i * U_ + lane * 4);
            aj[q]  = *(const float4*)(g_ajT + (size_t)i * U_ + lane * 4);
        }
        float part[4];
#pragma unroll
        for (int q = 0; q < 4; q++) {
            float p;
            p = fi[q].x * ai4.x;
            p = fmaf(fi[q].y, ai4.y, p);
            p = fmaf(fi[q].z, ai4.z, p);
            p = fmaf(fi[q].w, ai4.w, p);
            p = fmaf(fj4.x, aj[q].x, p);
            p = fmaf(fj4.y, aj[q].y, p);
            p = fmaf(fj4.z, aj[q].z, p);
            p = fmaf(fj4.w, aj[q].w, p);
            part[q] = p;
        }
#pragma unroll
        for (int off = 16; off; off >>= 1) {
#pragma unroll
            for (int q = 0; q < 4; q++)
                part[q] += __shfl_xor_sync(0xFFFFFFFFu, part[q], off);
        }
        float lg[4];
#pragma unroll
        for (int q = 0; q < 4; q++) {
            lg[q] = part[q] + ((enc[q] & 0x10000) ? 1.0e9f : 0.0f);
            if (lane == 0) s_lg[warp][e + q] = lg[q];
        }
        float bm = fmaxf(fmaxf(lg[0], lg[1]), fmaxf(lg[2], lg[3]));
        float newm  = fmaxf(m, bm);
        float scale = expf(m - newm);
        float p0 = expf(lg[0] - newm);
        float p1 = expf(lg[1] - newm);
        float p2 = expf(lg[2] - newm);
        float p3 = expf(lg[3] - newm);
        ssum = fmaf(ssum, scale, (p0 + p1) + (p2 + p3));
        acc.x = fmaf(acc.x, scale, fmaf(p0, fi[0].x, fmaf(p1, fi[1].x, fmaf(p2, fi[2].x, p3 * fi[3].x))));
        acc.y = fmaf(acc.y, scale, fmaf(p0, fi[0].y, fmaf(p1, fi[1].y, fmaf(p2, fi[2].y, p3 * fi[3].y))));
        acc.z = fmaf(acc.z, scale, fmaf(p0, fi[0].z, fmaf(p1, fi[1].z, fmaf(p2, fi[2].z, p3 * fi[3].z))));
        acc.w = fmaf(acc.w, scale, fmaf(p0, fi[0].w, fmaf(p1, fi[1].w, fmaf(p2, fi[2].w, p3 * fi[3].w))));
        m = newm;
    }
    for (; e < nnz; e++) {
        int enc = s_rows[e];
        int i   = enc & 0xFFFF;
        float4 cfi = *(const float4*)(fb + (size_t)i * U_ + lane * 4);
        float4 caj = *(const float4*)(g_ajT + (size_t)i * U_ + lane * 4);
        float part;
        part = cfi.x * ai4.x;
        part = fmaf(cfi.y, ai4.y, part);
        part = fmaf(cfi.z, ai4.z, part);
        part = fmaf(cfi.w, ai4.w, part);
        part = fmaf(fj4.x, caj.x, part);
        part = fmaf(fj4.y, caj.y, part);
        part = fmaf(fj4.z, caj.z, part);
        part = fmaf(fj4.w, caj.w, part);
#pragma unroll
        for (int off = 16; off; off >>= 1)
            part += __shfl_xor_sync(0xFFFFFFFFu, part, off);
        float lg = part + ((enc & 0x10000) ? 1.0e9f : 0.0f);
        if (lane == 0) s_lg[warp][e] = lg;
        float newm  = fmaxf(m, lg);
        float scale = expf(m - newm);
        float p     = expf(lg - newm);
        ssum  = fmaf(ssum, scale, p);
        acc.x = fmaf(acc.x, scale, p * cfi.x);
        acc.y = fmaf(acc.y, scale, p * cfi.y);
        acc.z = fmaf(acc.z, scale, p * cfi.z);
        acc.w = fmaf(acc.w, scale, p * cfi.w);
        m = newm;
    }
    __syncwarp();

    const float inv = 1.0f / ssum;

    // compact normalized p's (coalesced) — scatter happens in scatter_k
    if (write_attn) {
        float* pv = g_pvals + ((size_t)warp * N_ + j) * MAXNZ;
        for (int k = lane; k < nnz; k += 32)
            pv[k] = expf(s_lg[warp][k] - m) * inv;
    }

    float4 o;
    o.x = fmaxf(acc.x * inv, 0.0f);
    o.y = fmaxf(acc.y * inv, 0.0f);
    o.z = fmaxf(acc.z * inv, 0.0f);
    o.w = fmaxf(acc.w * inv, 0.0f);
    *(float4*)(out + ((size_t)warp * N_ + j) * U_ + lane * 4) = o;
}

// ======= scatter kernel: patch nonzeros into the zeroed attn ====================
__global__ __launch_bounds__(128) void scatter_k(float* __restrict__ attn) {
    const int j    = blockIdx.x;
    const int warp = threadIdx.x >> 5;
    const int lane = threadIdx.x & 31;
    const int nnz  = g_cnt[j];
    const int*   rows = g_rows + (size_t)j * MAXNZ;
    const float* pv   = g_pvals + ((size_t)warp * N_ + j) * MAXNZ;
    for (int e = lane; e < nnz; e += 32) {
        int i = rows[e] & 0xFFFF;
        attn[((size_t)warp * N_ + i) * N_ + j] = pv[e];
    }
}

// ---------------- launch: 3-node chain on the capture stream -------------------
extern "C" void kernel_launch(void* const* d_in, const int* in_sizes, int n_in,
                              void* d_out, int out_size) {
    const float* inputs = (const float*)d_in[0];   // [B,N,F]
    const float* w      = (const float*)d_in[1];   // [F,U]
    const float* ai     = (const float*)d_in[2];   // [U,N]
    const float* aj     = (const float*)d_in[3];   // [U,N]
    const float* adj    = (const float*)d_in[4];   // [N,N]

    const size_t OUT1 = (size_t)B_ * N_ * U_;
    const size_t ATTN = (size_t)B_ * N_ * N_;
    float* out_relu = (float*)d_out;
    float* attn = nullptr;
    if ((size_t)out_size >= OUT1 + ATTN) attn = (float*)d_out + OUT1;

    front_k<<<NB_FRONT, 256>>>(inputs, w, ai, aj, adj, attn);
    col_k<<<4096 / 2 * 3, 128>>>(out_relu, attn, attn != nullptr);
    if (attn) scatter_k<<<N_, 128>>>(attn);
}

// round 14
// speedup vs baseline: 1.1348x; 1.0972x over previous
#include <cuda_runtime.h>
#include <cuda_bf16.h>
#include <math.h>
#include <stdint.h>

// Problem constants
#define B_  4
#define N_  4096
#define F_  256
#define U_  128
#define M_  (B_ * N_)          // 16384 rows of f
#define MAXNZ 192

// prep_k roles, interleaved per group of 11: 8 build, 2 transpose, 1 gemm
// groups = 512 -> 4096 build, 1024 transpose, 512 gemm (64x64 tiles)
#define PREP_GROUPS 512
#define NB_PREP (PREP_GROUPS * 11)   // 5632

// ---------------- device scratch (no allocations allowed) ----------------
__device__ float g_f  [M_ * U_];        // f = inputs @ w   [B*N, U]   (8 MB)
__device__ float g_aiT[N_ * U_];        // ai^T [N, U]                 (2 MB)
__device__ float g_ajT[N_ * U_];        // aj^T [N, U]                 (2 MB)
__device__ int   g_rows[N_ * MAXNZ];    // per-column neighbor lists   (3 MB)
__device__ int   g_cnt [N_];

// ---------------- f32x2 packed-FMA helpers ----------------
__device__ __forceinline__ unsigned long long pk2(float x, float y) {
    unsigned long long r;
    asm("mov.b64 %0, {%1,%2};" : "=l"(r) : "f"(x), "f"(y));
    return r;
}
__device__ __forceinline__ void upk2(unsigned long long v, float& x, float& y) {
    asm("mov.b64 {%0,%1}, %2;" : "=f"(x), "=f"(y) : "l"(v));
}
__device__ __forceinline__ void ffma2(unsigned long long& d, unsigned long long a,
                                      unsigned long long b) {
    asm("fma.rn.f32x2 %0, %1, %2, %0;" : "+l"(d) : "l"(a), "l"(b));
}

// ============ prep kernel: GEMM(64x64) + build + transpose (NO fill) ===========
__global__ __launch_bounds__(256) void prep_k(const float* __restrict__ A,
                                              const float* __restrict__ W,
                                              const float* __restrict__ ai,
                                              const float* __restrict__ aj,
                                              const float* __restrict__ adj) {
    const int bid = blockIdx.x;
    const int tid = threadIdx.x;
    const int g   = bid / 11;
    const int r   = bid - g * 11;

    if (r < 8) {
        // -------- role BUILD: neighbor list for column j --------------------------
        const int j = g * 8 + r;        // [0, 4096)
        __shared__ int sc[256];
        const float* row = adj + (size_t)j * N_;

        int cnt = 0;
#pragma unroll
        for (int k = 0; k < 16; k++) {
            int i = k * 256 + tid;
            float v = row[i];
            if (i == j || v > 0.0f) cnt++;
        }
        sc[tid] = cnt;
        __syncthreads();
        for (int off = 1; off < 256; off <<= 1) {
            int add = (tid >= off) ? sc[tid - off] : 0;
            __syncthreads();
            sc[tid] += add;
            __syncthreads();
        }
        int pos = sc[tid] - cnt;
        int* dst = g_rows + (size_t)j * MAXNZ;
#pragma unroll
        for (int k = 0; k < 16; k++) {
            int i = k * 256 + tid;
            float v = row[i];
            if (i == j) {
                if (pos < MAXNZ) dst[pos] = i | ((v > 0.0f) ? 0x10000 : 0);
                pos++;
            } else if (v > 0.0f) {
                if (pos < MAXNZ) dst[pos] = i;
                pos++;
            }
        }
        if (tid == 255) g_cnt[j] = (sc[255] < MAXNZ) ? sc[255] : MAXNZ;
        return;
    }

    if (r < 10) {
        // -------- role TRANSPOSE: one 32x32 tile of ai or aj ----------------------
        __shared__ float tile[32][33];
        const int t   = g * 2 + (r - 8);   // [0, 1024)
        const int z   = t >> 9;            // 0 = ai, 1 = aj
        const int t2  = t & 511;
        const int n0  = (t2 & 127) * 32;
        const int u0  = (t2 >> 7) * 32;
        const float* src = z ? aj : ai;
        float* dst       = z ? g_ajT : g_aiT;
        const int tx = tid & 31, ty = tid >> 5;   // 32 x 8
#pragma unroll
        for (int rr = 0; rr < 32; rr += 8)
            tile[ty + rr][tx] = src[(size_t)(u0 + ty + rr) * N_ + n0 + tx];
        __syncthreads();
#pragma unroll
        for (int rr = 0; rr < 32; rr += 8)
            dst[(size_t)(n0 + ty + rr) * U_ + u0 + tx] = tile[tx][ty + rr];
        return;
    }

    // -------- role GEMM: f = inputs @ w, 64x64 tile, 4x4 micro (low regs) --------
    {
        __shared__ float As[32][68];    // [BK][BM+4] transposed A tile
        __shared__ float Bs[32][64];    // [BK][BN]
        const int gb = g;               // [0, 512)
        const int m0 = (gb >> 1) * 64;
        const int n0 = (gb & 1) * 64;
        const int tm = (tid >> 4) << 2;    // 0..60 step 4
        const int tn = (tid & 15) << 2;    // 0..60 step 4

        unsigned long long acc[4][2];
#pragma unroll
        for (int i = 0; i < 4; i++) { acc[i][0] = 0ull; acc[i][1] = 0ull; }

        for (int k0 = 0; k0 < F_; k0 += 32) {
            // A tile 64x32 -> transposed: 512 f4, 2 per thread
#pragma unroll
            for (int rr = 0; rr < 2; rr++) {
                int idx = tid + 256 * rr;
                int row = idx >> 3;          // 0..63
                int c4  = idx & 7;           // 0..7
                float4 v = *(const float4*)(A + (size_t)(m0 + row) * F_ + k0 + c4 * 4);
                As[c4 * 4 + 0][row] = v.x;
                As[c4 * 4 + 1][row] = v.y;
                As[c4 * 4 + 2][row] = v.z;
                As[c4 * 4 + 3][row] = v.w;
            }
            // W tile 32x64: 512 f4, 2 per thread
#pragma unroll
            for (int rr = 0; rr < 2; rr++) {
                int idx = tid + 256 * rr;
                int row = idx >> 4;          // 0..31
                int c4  = idx & 15;          // 0..15
                *(float4*)&Bs[row][c4 * 4] =
                    *(const float4*)(W + (size_t)(k0 + row) * U_ + n0 + c4 * 4);
            }
            __syncthreads();
#pragma unroll
            for (int kk = 0; kk < 32; kk++) {
                float a[4];
                *(float4*)&a[0] = *(const float4*)&As[kk][tm];
                ulonglong2 b2 = *(const ulonglong2*)&Bs[kk][tn];
                unsigned long long b0 = b2.x, b1 = b2.y;
#pragma unroll
                for (int i = 0; i < 4; i++) {
                    unsigned long long ar = pk2(a[i], a[i]);
                    ffma2(acc[i][0], ar, b0);
                    ffma2(acc[i][1], ar, b1);
                }
            }
            __syncthreads();
        }
#pragma unroll
        for (int i = 0; i < 4; i++) {
            float x0, x1, x2, x3;
            upk2(acc[i][0], x0, x1);
            upk2(acc[i][1], x2, x3);
            *(float4*)(g_f + (size_t)(m0 + tm + i) * U_ + n0 + tn) =
                make_float4(x0, x1, x2, x3);
        }
    }
}

// ---------------- col kernel (R11, measured 47.3us): online softmax, 4-edge batch
// one block per column j, warp b = batch b. lane owns u = lane*4 .. +3
__global__ __launch_bounds__(128) void col_k(float* __restrict__ out,
                                             float* __restrict__ attn,
                                             int write_attn) {
    const int j    = blockIdx.x;
    const int warp = threadIdx.x >> 5;
    const int lane = threadIdx.x & 31;

    __shared__ float s_lg[B_][MAXNZ];
    __shared__ int   s_rows[MAXNZ];

    const int nnz = g_cnt[j];
    for (int e = threadIdx.x; e < nnz; e += 128)
        s_rows[e] = g_rows[(size_t)j * MAXNZ + e];
    __syncthreads();

    const float* fb = g_f + (size_t)warp * N_ * U_;
    const float4 fj4 = *(const float4*)(fb + (size_t)j * U_ + lane * 4);
    const float4 ai4 = *(const float4*)(g_aiT + (size_t)j * U_ + lane * 4);

    float  m    = -3.0e38f;
    float  ssum = 0.0f;
    float4 acc  = make_float4(0.f, 0.f, 0.f, 0.f);

    int e = 0;
    for (; e + 4 <= nnz; e += 4) {
        int    enc[4];
        float4 fi[4], aj[4];
#pragma unroll
        for (int q = 0; q < 4; q++) {
            enc[q] = s_rows[e + q];
            int i  = enc[q] & 0xFFFF;
            fi[q]  = *(const float4*)(fb + (size_t)i * U_ + lane * 4);
            aj[q]  = *(const float4*)(g_ajT + (size_t)i * U_ + lane * 4);
        }
        float part[4];
#pragma unroll
        for (int q = 0; q < 4; q++) {
            float p;
            p = fi[q].x * ai4.x;
            p = fmaf(fi[q].y, ai4.y, p);
            p = fmaf(fi[q].z, ai4.z, p);
            p = fmaf(fi[q].w, ai4.w, p);
            p = fmaf(fj4.x, aj[q].x, p);
            p = fmaf(fj4.y, aj[q].y, p);
            p = fmaf(fj4.z, aj[q].z, p);
            p = fmaf(fj4.w, aj[q].w, p);
            part[q] = p;
        }
#pragma unroll
        for (int off = 16; off; off >>= 1) {
#pragma unroll
            for (int q = 0; q < 4; q++)
                part[q] += __shfl_xor_sync(0xFFFFFFFFu, part[q], off);
        }
        float lg[4];
#pragma unroll
        for (int q = 0; q < 4; q++) {
            lg[q] = part[q] + ((enc[q] & 0x10000) ? 1.0e9f : 0.0f);
            if (lane == 0) s_lg[warp][e + q] = lg[q];
        }
        float bm = fmaxf(fmaxf(lg[0], lg[1]), fmaxf(lg[2], lg[3]));
        float newm  = fmaxf(m, bm);
        float scale = expf(m - newm);
        float p0 = expf(lg[0] - newm);
        float p1 = expf(lg[1] - newm);
        float p2 = expf(lg[2] - newm);
        float p3 = expf(lg[3] - newm);
        ssum = fmaf(ssum, scale, (p0 + p1) + (p2 + p3));
        acc.x = fmaf(acc.x, scale, fmaf(p0, fi[0].x, fmaf(p1, fi[1].x, fmaf(p2, fi[2].x, p3 * fi[3].x))));
        acc.y = fmaf(acc.y, scale, fmaf(p0, fi[0].y, fmaf(p1, fi[1].y, fmaf(p2, fi[2].y, p3 * fi[3].y))));
        acc.z = fmaf(acc.z, scale, fmaf(p0, fi[0].z, fmaf(p1, fi[1].z, fmaf(p2, fi[2].z, p3 * fi[3].z))));
        acc.w = fmaf(acc.w, scale, fmaf(p0, fi[0].w, fmaf(p1, fi[1].w, fmaf(p2, fi[2].w, p3 * fi[3].w))));
        m = newm;
    }
    for (; e < nnz; e++) {
        int enc = s_rows[e];
        int i   = enc & 0xFFFF;
        float4 cfi = *(const float4*)(fb + (size_t)i * U_ + lane * 4);
        float4 caj = *(const float4*)(g_ajT + (size_t)i * U_ + lane * 4);
        float part;
        part = cfi.x * ai4.x;
        part = fmaf(cfi.y, ai4.y, part);
        part = fmaf(cfi.z, ai4.z, part);
        part = fmaf(cfi.w, ai4.w, part);
        part = fmaf(fj4.x, caj.x, part);
        part = fmaf(fj4.y, caj.y, part);
        part = fmaf(fj4.z, caj.z, part);
        part = fmaf(fj4.w, caj.w, part);
#pragma unroll
        for (int off = 16; off; off >>= 1)
            part += __shfl_xor_sync(0xFFFFFFFFu, part, off);
        float lg = part + ((enc & 0x10000) ? 1.0e9f : 0.0f);
        if (lane == 0) s_lg[warp][e] = lg;
        float newm  = fmaxf(m, lg);
        float scale = expf(m - newm);
        float p     = expf(lg - newm);
        ssum  = fmaf(ssum, scale, p);
        acc.x = fmaf(acc.x, scale, p * cfi.x);
        acc.y = fmaf(acc.y, scale, p * cfi.y);
        acc.z = fmaf(acc.z, scale, p * cfi.z);
        acc.w = fmaf(acc.w, scale, p * cfi.w);
        m = newm;
    }
    __syncwarp();

    const float inv = 1.0f / ssum;

    if (write_attn) {
        for (int k = lane; k < nnz; k += 32) {
            int i = s_rows[k] & 0xFFFF;
            attn[((size_t)warp * N_ + i) * N_ + j] = expf(s_lg[warp][k] - m) * inv;
        }
    }

    float4 o;
    o.x = fmaxf(acc.x * inv, 0.0f);
    o.y = fmaxf(acc.y * inv, 0.0f);
    o.z = fmaxf(acc.z * inv, 0.0f);
    o.w = fmaxf(acc.w * inv, 0.0f);
    *(float4*)(out + ((size_t)warp * N_ + j) * U_ + lane * 4) = o;
}

// ---------------- launch: memset -> prep -> col (simple serial chain) ----------
extern "C" void kernel_launch(void* const* d_in, const int* in_sizes, int n_in,
                              void* d_out, int out_size) {
    const float* inputs = (const float*)d_in[0];   // [B,N,F]
    const float* w      = (const float*)d_in[1];   // [F,U]
    const float* ai     = (const float*)d_in[2];   // [U,N]
    const float* aj     = (const float*)d_in[3];   // [U,N]
    const float* adj    = (const float*)d_in[4];   // [N,N]

    const size_t OUT1 = (size_t)B_ * N_ * U_;
    const size_t ATTN = (size_t)B_ * N_ * N_;
    float* out_relu = (float*)d_out;
    float* attn = nullptr;
    if ((size_t)out_size >= OUT1 + ATTN) attn = (float*)d_out + OUT1;

    if (attn) cudaMemsetAsync(attn, 0, ATTN * sizeof(float), 0);
    prep_k<<<NB_PREP, 256>>>(inputs, w, ai, aj, adj);
    col_k<<<N_, 128>>>(out_relu, attn, attn != nullptr);
}